// round 4
// baseline (speedup 1.0000x reference)
#include <cuda_runtime.h>
#include <cuda_bf16.h>
#include <cstdint>

// Problem shape (fixed by the reference)
#define BB 8
#define CC 16
#define HH 512
#define WW 1024

// One thread handles 4 consecutive-w pixels of one (b,h) row.
// disp is shared across the 16 channels: compute x0/x1/weights once per pixel,
// then loop channels. Per channel iteration: 8 gather loads (L1-adjacent) and
// one aligned float4 store. W and total pixel count are exact multiples of
// 4*256, so no bounds checks.
__global__ __launch_bounds__(256) void warp_disp_kernel(
    const float* __restrict__ input,   // [B,C,H,W]
    const float* __restrict__ disp,    // [B,1,H,W]
    float* __restrict__ out)           // [B,C,H,W]
{
    const int tid = blockIdx.x * blockDim.x + threadIdx.x;   // 1M threads
    const int w0  = (tid * 4) & (WW - 1);                    // 0..1020, step 4
    const int bh  = tid / (WW / 4);                          // b*H + h
    const int h   = bh & (HH - 1);
    const int b   = bh >> 9;                                 // /HH

    // disp layout [B,1,H,W] == [B*H*W]; aligned float4 load
    const float4 d4 = *(const float4*)(disp + (int64_t)bh * WW + w0);

    int   x0[4], x1[4];
    float wl[4], wr[4];
    const float dvals[4] = {d4.x, d4.y, d4.z, d4.w};
    #pragma unroll
    for (int i = 0; i < 4; ++i) {
        float x = (float)(w0 + i) + dvals[i];
        x = fminf(fmaxf(x, 0.0f), (float)(WW - 1));
        const float x0f = floorf(x);
        const float x1f = fminf(x0f + 1.0f, (float)(WW - 1));
        x0[i] = (int)x0f;
        x1[i] = (int)x1f;
        wl[i] = x1f - x;          // note: NOT 1-wr; both 0 at the right clamp
        wr[i] = x - x0f;
    }

    // base pointer for channel 0 of this (b,h) row
    const float* in_row = input + (((int64_t)b * CC * HH + h) * WW);
    float*      out_row = out   + (((int64_t)b * CC * HH + h) * WW) + w0;
    const int cstride = HH * WW;   // 524288, fits in int

    #pragma unroll 4
    for (int c = 0; c < CC; ++c) {
        const float* rc = in_row + (int64_t)c * cstride;
        float4 r;
        r.x = wl[0] * __ldg(rc + x0[0]) + wr[0] * __ldg(rc + x1[0]);
        r.y = wl[1] * __ldg(rc + x0[1]) + wr[1] * __ldg(rc + x1[1]);
        r.z = wl[2] * __ldg(rc + x0[2]) + wr[2] * __ldg(rc + x1[2]);
        r.w = wl[3] * __ldg(rc + x0[3]) + wr[3] * __ldg(rc + x1[3]);
        *(float4*)(out_row + (int64_t)c * cstride) = r;
    }
}

extern "C" void kernel_launch(void* const* d_in, const int* in_sizes, int n_in,
                              void* d_out, int out_size) {
    const float* input = (const float*)d_in[0];
    const float* disp  = (const float*)d_in[1];
    float* out = (float*)d_out;

    const int n_threads = BB * HH * (WW / 4);   // 1,048,576
    const int threads = 256;
    warp_disp_kernel<<<n_threads / threads, threads>>>(input, disp, out);
}